// round 16
// baseline (speedup 1.0000x reference)
#include <cuda_runtime.h>
#include <math.h>

#define NMAX 10000
#define EMAX 320000

// ---------------- scratch (device globals; no allocation allowed) -------------
__device__ int      g_is64;
__device__ float    g_deg[NMAX];
__device__ float    g_dis[NMAX];
__device__ int      g_cnt[NMAX];
__device__ int      g_rowptr[NMAX + 1];
__device__ int      g_srcd[EMAX];
__device__ int      g_dstd[EMAX];
__device__ int2     g_colw[EMAX];            // packed (src col, bitcast norm)
__device__ unsigned g_arrive;                // invariant: 0 between barriers
__device__ volatile unsigned g_gen;          // generation counter (any start value)
__device__ __align__(256) float g_h[NMAX * 64];
__device__ __align__(256) float g_acc[NMAX * 64];
__device__ __align__(256) float g_B0[NMAX * 64];
__device__ __align__(256) float g_B1[NMAX * 64];
__device__ __align__(256) float g_B2[NMAX * 64];

constexpr int TPB  = 512;
constexpr int NPB  = 16;    // nodes per pass (one per warp)
constexpr int BPS  = 4;     // resident blocks per SM (64 warps/SM -> 100% occ)
constexpr int ST   = 68;    // smem row stride (floats); 68 mod 32 = 4 -> LDS.128 ok
constexpr int TSR  = 32;    // Ts rows: 2 passes x 16 warps

// ---------------- split grid barrier, RELATIVE generation (replay-safe) -------
__device__ __forceinline__ unsigned bar_arrive(int G) {
    unsigned gen = 0;
    if (threadIdx.x == 0) {
        gen = g_gen;
        if (atomicAdd(&g_arrive, 1u) == (unsigned)G - 1u) {
            g_arrive = 0u;
            __threadfence();
            g_gen = gen + 1u;   // release (single writer per generation)
        }
    }
    return gen;   // meaningful in tid 0 only
}
__device__ __forceinline__ void bar_wait(unsigned gen) {
    __syncthreads();   // all threads of block done with overlapped work
    if (threadIdx.x == 0) {
        while (g_gen == gen) { __nanosleep(32); }
        __threadfence();
    }
    __syncthreads();
}
__device__ __forceinline__ void gbar_full(int G) {
    __threadfence();
    __syncthreads();
    unsigned gen = bar_arrive(G);
    bar_wait(gen);
}

__device__ __forceinline__ float silu_f(float v) {
    return v / (1.f + expf(-v));
}

// ---------------- per-layer device routine ------------------------------------
// Warp owns one node per pass (proven chunked gather + meta prefetch);
// passes fill Ts; block GEMM runs BETWEEN barrier arrive and wait.
// Last step's GEMM epilogue writes silu(acc) into hout.
// SAFETY: hout must not be read by other blocks during the final step
// (h0 qualifies: read only at k<=2; acc qualifies: block-owned rows).
template <int IN, int OUT>
__device__ __forceinline__ void layer_run(const float* __restrict__ h0,
                                          float* __restrict__ acc,
                                          float* __restrict__ hout,
                                          const float* __restrict__ W,
                                          const float* __restrict__ bias,
                                          int K, int n, int G,
                                          float* Ts, float* WsT) {
    int tid  = threadIdx.x;
    int wrp  = tid >> 5;
    int lane = tid & 31;

    const float* src = h0;      // T_{k-1}
    const float* prv = nullptr; // T_{k-2}
    float* rot0 = g_B1; float* rot1 = g_B2; float* rot2 = g_B0;

    int tiles = (n + G * NPB - 1) / (G * NPB);   // <= 2 by construction

    // stage W_0 (visible to the GEMM via the post-gather __syncthreads)
    for (int idx = tid; idx < IN * OUT; idx += TPB) {
        int i = idx / OUT, j2 = idx % OUT;
        WsT[j2 * ST + i] = W[idx];
    }

    for (int k = 0; k < K; k++) {
        float* dst = nullptr;
        if (k >= 1) {
            int r = (k - 1) % 3;
            dst = (r == 0) ? rot0 : (r == 1) ? rot1 : rot2;
        }

        // ---- gather passes (warps own distinct Ts rows)
        for (int p = 0; p < tiles; p++) {
            int base = (p * G + blockIdx.x) * NPB;
            int nd = base + wrp;
            float* tsw = Ts + (p * NPB + wrp) * ST;
            if (nd < n) {
                if (k == 0) {
                    for (int f = lane; f < IN; f += 32) tsw[f] = h0[nd * IN + f];
                } else if (IN == 4) {
                    // lane-per-edge float4 gather
                    int beg = g_rowptr[nd], end = g_rowptr[nd + 1];
                    float4 s = make_float4(0.f, 0.f, 0.f, 0.f);
                    for (int e = beg + lane; e < end; e += 32) {
                        int2 cw = __ldg(&g_colw[e]);
                        float nv = __int_as_float(cw.y);
                        float4 v = __ldg((const float4*)(src + cw.x * 4));
                        s.x += nv * v.x; s.y += nv * v.y;
                        s.z += nv * v.z; s.w += nv * v.w;
                    }
#pragma unroll
                    for (int off = 16; off >= 1; off >>= 1) {
                        s.x += __shfl_xor_sync(0xffffffffu, s.x, off);
                        s.y += __shfl_xor_sync(0xffffffffu, s.y, off);
                        s.z += __shfl_xor_sync(0xffffffffu, s.z, off);
                        s.w += __shfl_xor_sync(0xffffffffu, s.w, off);
                    }
                    if (lane == 0) {
                        float4 t = s;
                        if (k >= 2) {
                            float4 q = __ldg((const float4*)(prv + nd * 4));
                            t.x = 2.f * s.x - q.x; t.y = 2.f * s.y - q.y;
                            t.z = 2.f * s.z - q.z; t.w = 2.f * s.w - q.w;
                        }
                        *((float4*)(dst + nd * 4)) = t;
                        tsw[0] = t.x; tsw[1] = t.y; tsw[2] = t.z; tsw[3] = t.w;
                    }
                } else if (IN % 16 == 0) {
                    // chunked gather with META PREFETCH
                    int beg = g_rowptr[nd], end = g_rowptr[nd + 1];
                    int half = lane >> 4;
                    int fl   = lane & 15;
                    float4 a0 = make_float4(0.f, 0.f, 0.f, 0.f);
                    float4 a1 = make_float4(0.f, 0.f, 0.f, 0.f);
                    int cb = beg;
                    int ce = end - cb; if (ce > 32) ce = 32;
                    int2 meta = make_int2(0, 0);
                    if (cb < end && lane < ce) meta = __ldg(&g_colw[cb + lane]);
                    while (cb < end) {
                        int2 cur = meta;
                        int cce = ce;
                        int nb = cb + 32;
                        if (nb < end) {
                            int ne = end - nb; if (ne > 32) ne = 32;
                            if (lane < ne) meta = __ldg(&g_colw[nb + lane]);
                            ce = ne;
                        }
                        int jj = 0;
                        for (; jj + 3 < cce; jj += 4) {
                            int e0 = jj + half;
                            int e1 = jj + 2 + half;
                            int c0 = __shfl_sync(0xffffffffu, cur.x, e0);
                            int w0 = __shfl_sync(0xffffffffu, cur.y, e0);
                            int c1 = __shfl_sync(0xffffffffu, cur.x, e1);
                            int w1 = __shfl_sync(0xffffffffu, cur.y, e1);
                            float4 v0 = __ldg(((const float4*)(src + c0 * IN)) + fl);
                            float4 v1 = __ldg(((const float4*)(src + c1 * IN)) + fl);
                            float n0 = __int_as_float(w0);
                            float n1 = __int_as_float(w1);
                            a0.x += n0 * v0.x; a0.y += n0 * v0.y;
                            a0.z += n0 * v0.z; a0.w += n0 * v0.w;
                            a1.x += n1 * v1.x; a1.y += n1 * v1.y;
                            a1.z += n1 * v1.z; a1.w += n1 * v1.w;
                        }
                        for (; jj < cce; jj += 2) {
                            int e0 = jj + half;
                            int idx = (e0 < cce) ? e0 : (cce - 1);
                            int c0 = __shfl_sync(0xffffffffu, cur.x, idx);
                            int w0 = __shfl_sync(0xffffffffu, cur.y, idx);
                            float n0 = (e0 < cce) ? __int_as_float(w0) : 0.f;
                            float4 v0 = __ldg(((const float4*)(src + c0 * IN)) + fl);
                            a0.x += n0 * v0.x; a0.y += n0 * v0.y;
                            a0.z += n0 * v0.z; a0.w += n0 * v0.w;
                        }
                        cb = nb;
                    }
                    float4 s = make_float4(a0.x + a1.x, a0.y + a1.y,
                                           a0.z + a1.z, a0.w + a1.w);
                    s.x += __shfl_xor_sync(0xffffffffu, s.x, 16);
                    s.y += __shfl_xor_sync(0xffffffffu, s.y, 16);
                    s.z += __shfl_xor_sync(0xffffffffu, s.z, 16);
                    s.w += __shfl_xor_sync(0xffffffffu, s.w, 16);
                    if (lane < 16) {
                        float4 t = s;
                        if (k >= 2) {
                            float4 q = __ldg(((const float4*)(prv + nd * IN)) + fl);
                            t.x = 2.f * s.x - q.x; t.y = 2.f * s.y - q.y;
                            t.z = 2.f * s.z - q.z; t.w = 2.f * s.w - q.w;
                        }
                        ((float4*)(dst + nd * IN))[fl] = t;
                        ((float4*)tsw)[fl] = t;
                    }
                } else {
                    // odd width (IN=60): lane-per-feature scalar path
                    int beg = g_rowptr[nd], end = g_rowptr[nd + 1];
                    int f0 = lane, f1 = lane + 32;
                    float s0 = 0.f, s1 = 0.f;
                    for (int e = beg; e < end; e++) {
                        int2 cw = __ldg(&g_colw[e]);
                        float nv = __int_as_float(cw.y);
                        const float* rp = src + cw.x * IN;
                        s0 += nv * __ldg(&rp[f0]);
                        if (f1 < IN) s1 += nv * __ldg(&rp[f1]);
                    }
                    {
                        float t0 = (k >= 2) ? 2.f * s0 - prv[nd * IN + f0] : s0;
                        dst[nd * IN + f0] = t0;
                        tsw[f0] = t0;
                    }
                    if (f1 < IN) {
                        float t1 = (k >= 2) ? 2.f * s1 - prv[nd * IN + f1] : s1;
                        dst[nd * IN + f1] = t1;
                        tsw[f1] = t1;
                    }
                }
            }
        }

        // T_k globally visible, then ARRIVE EARLY — GEMM overlaps the barrier.
        __threadfence();
        __syncthreads();
        unsigned gen = bar_arrive(G);

        // ---- block GEMM over tiles*NPB rows (acc/hout rows owned per node)
        {
            int j = tid & 63;
            int g = tid >> 6;   // 0..7 groups of 4 rows = 32 rows
            if (j < OUT) {
                int nrows = tiles * NPB;
                for (int rb = 0; rb < nrows; rb += 32) {
                    int baserow = rb + g * 4;
                    float a0 = 0.f, a1 = 0.f, a2 = 0.f, a3 = 0.f;
                    const float4* wrow = (const float4*)(WsT + j * ST);
#pragma unroll 4
                    for (int ic = 0; ic < IN / 4; ic++) {
                        float4 wv = wrow[ic];
                        float4 t0 = ((const float4*)(Ts + (baserow + 0) * ST))[ic];
                        float4 t1 = ((const float4*)(Ts + (baserow + 1) * ST))[ic];
                        float4 t2 = ((const float4*)(Ts + (baserow + 2) * ST))[ic];
                        float4 t3 = ((const float4*)(Ts + (baserow + 3) * ST))[ic];
                        a0 += t0.x * wv.x + t0.y * wv.y + t0.z * wv.z + t0.w * wv.w;
                        a1 += t1.x * wv.x + t1.y * wv.y + t1.z * wv.z + t1.w * wv.w;
                        a2 += t2.x * wv.x + t2.y * wv.y + t2.z * wv.z + t2.w * wv.w;
                        a3 += t3.x * wv.x + t3.y * wv.y + t3.z * wv.z + t3.w * wv.w;
                    }
                    float av[4] = {a0, a1, a2, a3};
#pragma unroll
                    for (int q = 0; q < 4; q++) {
                        int r = baserow + q;
                        int node = ((r >> 4) * G + blockIdx.x) * NPB + (r & 15);
                        if (r < nrows && node < n) {
                            if (k == 0) {
                                acc[node * OUT + j] = av[q] + __ldg(&bias[j]);
                            } else if (k == K - 1) {
                                // fold SiLU into the last step
                                hout[node * OUT + j] =
                                    silu_f(acc[node * OUT + j] + av[q]);
                            } else {
                                acc[node * OUT + j] += av[q];
                            }
                        }
                    }
                }
            }
        }

        bar_wait(gen);   // all blocks' T_k visible; this block's GEMM done

        // stage W_{k+1}
        if (k + 1 < K) {
            for (int idx = tid; idx < IN * OUT; idx += TPB) {
                int i = idx / OUT, j2 = idx % OUT;
                WsT[j2 * ST + i] = W[(k + 1) * IN * OUT + idx];
            }
        }

        if (k >= 1) { prv = src; src = dst; }
    }

    // publish hout (written after the last arrive) before caller reads
    gbar_full(G);
}

// ---------------- the single fused kernel -------------------------------------
__global__ __launch_bounds__(TPB, BPS)
void fused_all(const float* __restrict__ x, const void* __restrict__ ei,
               const float* __restrict__ ew,
               const float* __restrict__ W1, const float* __restrict__ b1,
               const float* __restrict__ W2, const float* __restrict__ b2,
               const float* __restrict__ W3, const float* __restrict__ b3,
               const float* __restrict__ W4,
               float* __restrict__ out, int n, int E, int G) {
    __shared__ __align__(16) float Ts[TSR * ST];
    __shared__ __align__(16) float WsT[64 * ST];
    __shared__ int ssum[TPB];

    int tid = threadIdx.x;
    int bid = blockIdx.x;
    int gsz = G * TPB;
    int gid = bid * TPB + tid;

    // phase 0: zero counters + detect int64-vs-int32 edge_index layout
    for (int i = gid; i < n; i += gsz) { g_deg[i] = 0.f; g_cnt[i] = 0; }
    if (bid == 0) {
        __shared__ int bad;
        if (tid == 0) bad = 0;
        __syncthreads();
        int nsamp = E / 2;
        if (nsamp > 4096) nsamp = 4096;
        const int* p32 = (const int*)ei;
        for (int i = tid; i < nsamp; i += TPB)
            if (p32[2 * i + 1] != 0) bad = 1;
        __syncthreads();
        if (tid == 0) g_is64 = (bad == 0) ? 1 : 0;
    }
    gbar_full(G);

    // phase 1: decode edges (clamped) + degree & in-count
    {
        int is64 = g_is64;
        for (int e = gid; e < E; e += gsz) {
            int s, d;
            if (is64) {
                const long long* p = (const long long*)ei;
                s = (int)p[e];
                d = (int)p[(long long)E + e];
            } else {
                const int* p = (const int*)ei;
                s = p[e];
                d = p[E + e];
            }
            s = (s < 0) ? 0 : ((s >= n) ? n - 1 : s);
            d = (d < 0) ? 0 : ((d >= n) ? n - 1 : d);
            g_srcd[e] = s;
            g_dstd[e] = d;
            atomicAdd(&g_deg[s], ew[e]);
            atomicAdd(&g_cnt[d], 1);
        }
    }
    gbar_full(G);

    // phase 2: dis + exclusive scan (block 0 only)
    if (bid == 0) {
        for (int i = tid; i < n; i += TPB) {
            float d = g_deg[i];
            g_dis[i] = (d > 0.f) ? (1.f / sqrtf(d)) : 0.f;
        }
        __syncthreads();
        int chunk = (n + TPB - 1) / TPB;
        int beg = tid * chunk; if (beg > n) beg = n;
        int end = beg + chunk; if (end > n) end = n;
        int s = 0;
        for (int i = beg; i < end; i++) s += g_cnt[i];
        ssum[tid] = s;
        __syncthreads();
        for (int off = 1; off < TPB; off <<= 1) {
            int v = (tid >= off) ? ssum[tid - off] : 0;
            __syncthreads();
            ssum[tid] += v;
            __syncthreads();
        }
        int run = (tid == 0) ? 0 : ssum[tid - 1];
        for (int i = beg; i < end; i++) {
            int c = g_cnt[i];
            g_rowptr[i] = run;
            g_cnt[i] = run;   // cursor for scatter
            run += c;
        }
        if (tid == TPB - 1) g_rowptr[n] = ssum[TPB - 1];
    }
    gbar_full(G);

    // phase 3: scatter packed (col, norm) into CSR order
    for (int e = gid; e < E; e += gsz) {
        int s = g_srcd[e], d = g_dstd[e];
        float nv = -g_dis[s] * ew[e] * g_dis[d];
        int p = atomicAdd(&g_cnt[d], 1);
        g_colw[p] = make_int2(s, __float_as_int(nv));
    }
    gbar_full(G);

    // layer 1: ChebConv(4 -> 64, K=120) + SiLU folded into g_h
    layer_run<4, 64>(x, g_acc, g_h, W1, b1, 120, n, G, Ts, WsT);

    // layer 2: ChebConv(64 -> 60, K=120) + SiLU folded into g_h
    // (h0 == g_h is read only at k<=2, never during the final step -> safe)
    layer_run<64, 60>(g_h, g_acc, g_h, W2, b2, 120, n, G, Ts, WsT);

    // layer 3: ChebConv(60 -> 30, K=20) + SiLU folded into g_acc (block-owned)
    layer_run<60, 30>(g_h, g_acc, g_acc, W3, b3, 20, n, G, Ts, WsT);

    // layer 4: ChebConv(30 -> 1, K=1) + sigmoid
    for (int i = gid; i < n; i += gsz) {
        float s = 0.f;
        const float* hp = g_acc + i * 30;
#pragma unroll
        for (int k = 0; k < 30; k++) s += hp[k] * __ldg(&W4[k]);
        out[i] = 1.f / (1.f + expf(-s));
    }
}

// ---------------- host orchestration ------------------------------------------
extern "C" void kernel_launch(void* const* d_in, const int* in_sizes, int n_in,
                              void* d_out, int out_size) {
    const float* x  = (const float*)d_in[0];
    const void*  ei = d_in[1];
    const float* ew = (const float*)d_in[2];
    const float* W1 = (const float*)d_in[3];
    const float* b1 = (const float*)d_in[4];
    const float* W2 = (const float*)d_in[5];
    const float* b2 = (const float*)d_in[6];
    const float* W3 = (const float*)d_in[7];
    const float* b3 = (const float*)d_in[8];
    const float* W4 = (const float*)d_in[9];
    float* out = (float*)d_out;

    int n = in_sizes[0] / 4;   // 10000
    int E = in_sizes[2];       // 320000

    static int G = 0;
    if (G == 0) {
        int dev = 0;
        cudaGetDevice(&dev);
        int sms = 0;
        cudaDeviceGetAttribute(&sms, cudaDevAttrMultiProcessorCount, dev);
        int bps = 0;
        cudaOccupancyMaxActiveBlocksPerMultiprocessor(&bps, fused_all, TPB, 0);
        if (sms <= 0) sms = 148;
        if (bps <= 0) bps = 1;
        if (bps > BPS) bps = BPS;
        G = sms * bps;
        // need tiles = ceil(n/(G*16)) <= 2  ->  G >= n/32
        int min_g = (10000 + 31) / 32;
        if (G < min_g) G = min_g;
    }

    fused_all<<<G, TPB>>>(x, ei, ew, W1, b1, W2, b2, W3, b3, W4, out, n, E, G);
}

// round 17
// speedup vs baseline: 1.2859x; 1.2859x over previous
#include <cuda_runtime.h>
#include <math.h>

#define NMAX 10000
#define EMAX 320000

// ---------------- scratch (device globals; no allocation allowed) -------------
__device__ int      g_is64;
__device__ float    g_deg[NMAX];
__device__ float    g_dis[NMAX];
__device__ int      g_cnt[NMAX];
__device__ int      g_rowptr[NMAX + 1];
__device__ int      g_srcd[EMAX];
__device__ int      g_dstd[EMAX];
__device__ int2     g_colw[EMAX];            // packed (src col, bitcast norm)
__device__ unsigned g_arrive;                // invariant: 0 between barriers
__device__ volatile unsigned g_gen;          // generation counter (any start value)
__device__ __align__(256) float g_h[NMAX * 64];
__device__ __align__(256) float g_acc[NMAX * 64];
__device__ __align__(256) float g_B0[NMAX * 64];
__device__ __align__(256) float g_B1[NMAX * 64];
__device__ __align__(256) float g_B2[NMAX * 64];

constexpr int TPB  = 512;
constexpr int NPB  = 16;    // nodes per pass (one per warp)
constexpr int BPS  = 3;     // resident blocks per SM (48 warps/SM, proven best)
constexpr int ST   = 68;    // smem row stride (floats); 68 mod 32 = 4 -> LDS.128 ok
constexpr int TSR  = 32;    // Ts rows: 2 passes x 16 warps

// ---------------- split grid barrier, RELATIVE generation (replay-safe) -------
__device__ __forceinline__ unsigned bar_arrive(int G) {
    unsigned gen = 0;
    if (threadIdx.x == 0) {
        gen = g_gen;
        if (atomicAdd(&g_arrive, 1u) == (unsigned)G - 1u) {
            g_arrive = 0u;
            __threadfence();
            g_gen = gen + 1u;   // release (single writer per generation)
        }
    }
    return gen;   // meaningful in tid 0 only
}
__device__ __forceinline__ void bar_wait(unsigned gen) {
    __syncthreads();   // all threads of block done with overlapped work
    if (threadIdx.x == 0) {
        while (g_gen == gen) { __nanosleep(32); }
        __threadfence();
    }
    __syncthreads();
}
__device__ __forceinline__ void gbar_full(int G) {
    __threadfence();
    __syncthreads();
    unsigned gen = bar_arrive(G);
    bar_wait(gen);
}

__device__ __forceinline__ float silu_f(float v) {
    return v / (1.f + expf(-v));
}

// ---------------- per-layer device routine ------------------------------------
// INP: padded feature stride (4 or 64); INW: actual W input dim (<= INP);
// OUT: output dim; OUTS: output stride. W rows i>=INW staged as ZERO so pad
// columns never reach the output (propagate keeps pads bounded: |lambda|<=1).
// Warp owns one node per pass; block GEMM runs BETWEEN barrier arrive/wait.
// Last step folds SiLU into hout (hout must not be read by other blocks
// during the final step; h0 qualifies (read only k<=2), acc qualifies).
template <int INP, int INW, int OUT, int OUTS>
__device__ __forceinline__ void layer_run(const float* __restrict__ h0,
                                          float* __restrict__ acc,
                                          float* __restrict__ hout,
                                          const float* __restrict__ W,
                                          const float* __restrict__ bias,
                                          int K, int n, int G,
                                          float* Ts, float* WsT) {
    int tid  = threadIdx.x;
    int wrp  = tid >> 5;
    int lane = tid & 31;

    const float* src = h0;      // T_{k-1}
    const float* prv = nullptr; // T_{k-2}
    float* rot0 = g_B1; float* rot1 = g_B2; float* rot2 = g_B0;

    int tiles = (n + G * NPB - 1) / (G * NPB);   // <= 2 by construction

    // stage W_0 transposed + zero-padded: WsT[j*ST + i]
    for (int idx = tid; idx < INP * OUT; idx += TPB) {
        int i = idx / OUT, j2 = idx % OUT;
        WsT[j2 * ST + i] = (i < INW) ? W[i * OUT + j2] : 0.f;
    }

    for (int k = 0; k < K; k++) {
        float* dst = nullptr;
        if (k >= 1) {
            int r = (k - 1) % 3;
            dst = (r == 0) ? rot0 : (r == 1) ? rot1 : rot2;
        }

        // ---- gather passes (warps own distinct Ts rows)
        for (int p = 0; p < tiles; p++) {
            int base = (p * G + blockIdx.x) * NPB;
            int nd = base + wrp;
            float* tsw = Ts + (p * NPB + wrp) * ST;
            if (nd < n) {
                if (k == 0) {
                    for (int f = lane; f < INP; f += 32) tsw[f] = h0[nd * INP + f];
                } else if (INP == 4) {
                    // lane-per-edge float4 gather
                    int beg = g_rowptr[nd], end = g_rowptr[nd + 1];
                    float4 s = make_float4(0.f, 0.f, 0.f, 0.f);
                    for (int e = beg + lane; e < end; e += 32) {
                        int2 cw = __ldg(&g_colw[e]);
                        float nv = __int_as_float(cw.y);
                        float4 v = __ldg((const float4*)(src + cw.x * 4));
                        s.x += nv * v.x; s.y += nv * v.y;
                        s.z += nv * v.z; s.w += nv * v.w;
                    }
#pragma unroll
                    for (int off = 16; off >= 1; off >>= 1) {
                        s.x += __shfl_xor_sync(0xffffffffu, s.x, off);
                        s.y += __shfl_xor_sync(0xffffffffu, s.y, off);
                        s.z += __shfl_xor_sync(0xffffffffu, s.z, off);
                        s.w += __shfl_xor_sync(0xffffffffu, s.w, off);
                    }
                    if (lane == 0) {
                        float4 t = s;
                        if (k >= 2) {
                            float4 q = __ldg((const float4*)(prv + nd * 4));
                            t.x = 2.f * s.x - q.x; t.y = 2.f * s.y - q.y;
                            t.z = 2.f * s.z - q.z; t.w = 2.f * s.w - q.w;
                        }
                        *((float4*)(dst + nd * 4)) = t;
                        tsw[0] = t.x; tsw[1] = t.y; tsw[2] = t.z; tsw[3] = t.w;
                    }
                } else {
                    // chunked gather with META PREFETCH (INP == 64)
                    int beg = g_rowptr[nd], end = g_rowptr[nd + 1];
                    int half = lane >> 4;
                    int fl   = lane & 15;
                    float4 a0 = make_float4(0.f, 0.f, 0.f, 0.f);
                    float4 a1 = make_float4(0.f, 0.f, 0.f, 0.f);
                    int cb = beg;
                    int ce = end - cb; if (ce > 32) ce = 32;
                    int2 meta = make_int2(0, 0);
                    if (cb < end && lane < ce) meta = __ldg(&g_colw[cb + lane]);
                    while (cb < end) {
                        int2 cur = meta;
                        int cce = ce;
                        int nb = cb + 32;
                        if (nb < end) {
                            int ne = end - nb; if (ne > 32) ne = 32;
                            if (lane < ne) meta = __ldg(&g_colw[nb + lane]);
                            ce = ne;
                        }
                        int jj = 0;
                        for (; jj + 3 < cce; jj += 4) {
                            int e0 = jj + half;
                            int e1 = jj + 2 + half;
                            int c0 = __shfl_sync(0xffffffffu, cur.x, e0);
                            int w0 = __shfl_sync(0xffffffffu, cur.y, e0);
                            int c1 = __shfl_sync(0xffffffffu, cur.x, e1);
                            int w1 = __shfl_sync(0xffffffffu, cur.y, e1);
                            float4 v0 = __ldg(((const float4*)(src + c0 * INP)) + fl);
                            float4 v1 = __ldg(((const float4*)(src + c1 * INP)) + fl);
                            float n0 = __int_as_float(w0);
                            float n1 = __int_as_float(w1);
                            a0.x += n0 * v0.x; a0.y += n0 * v0.y;
                            a0.z += n0 * v0.z; a0.w += n0 * v0.w;
                            a1.x += n1 * v1.x; a1.y += n1 * v1.y;
                            a1.z += n1 * v1.z; a1.w += n1 * v1.w;
                        }
                        for (; jj < cce; jj += 2) {
                            int e0 = jj + half;
                            int idx = (e0 < cce) ? e0 : (cce - 1);
                            int c0 = __shfl_sync(0xffffffffu, cur.x, idx);
                            int w0 = __shfl_sync(0xffffffffu, cur.y, idx);
                            float n0 = (e0 < cce) ? __int_as_float(w0) : 0.f;
                            float4 v0 = __ldg(((const float4*)(src + c0 * INP)) + fl);
                            a0.x += n0 * v0.x; a0.y += n0 * v0.y;
                            a0.z += n0 * v0.z; a0.w += n0 * v0.w;
                        }
                        cb = nb;
                    }
                    float4 s = make_float4(a0.x + a1.x, a0.y + a1.y,
                                           a0.z + a1.z, a0.w + a1.w);
                    s.x += __shfl_xor_sync(0xffffffffu, s.x, 16);
                    s.y += __shfl_xor_sync(0xffffffffu, s.y, 16);
                    s.z += __shfl_xor_sync(0xffffffffu, s.z, 16);
                    s.w += __shfl_xor_sync(0xffffffffu, s.w, 16);
                    if (lane < 16) {
                        float4 t = s;
                        if (k >= 2) {
                            float4 q = __ldg(((const float4*)(prv + nd * INP)) + fl);
                            t.x = 2.f * s.x - q.x; t.y = 2.f * s.y - q.y;
                            t.z = 2.f * s.z - q.z; t.w = 2.f * s.w - q.w;
                        }
                        ((float4*)(dst + nd * INP))[fl] = t;
                        ((float4*)tsw)[fl] = t;
                    }
                }
            }
        }

        // T_k globally visible, then ARRIVE EARLY — GEMM overlaps the barrier.
        __threadfence();
        __syncthreads();
        unsigned gen = bar_arrive(G);

        // ---- block GEMM over tiles*NPB rows (acc/hout rows owned per node)
        {
            int j = tid & 63;
            int g = tid >> 6;   // 0..7 groups of 4 rows = 32 rows
            if (j < OUT) {
                int nrows = tiles * NPB;
                for (int rb = 0; rb < nrows; rb += 32) {
                    int baserow = rb + g * 4;
                    float a0 = 0.f, a1 = 0.f, a2 = 0.f, a3 = 0.f;
                    const float4* wrow = (const float4*)(WsT + j * ST);
#pragma unroll 4
                    for (int ic = 0; ic < INP / 4; ic++) {
                        float4 wv = wrow[ic];
                        float4 t0 = ((const float4*)(Ts + (baserow + 0) * ST))[ic];
                        float4 t1 = ((const float4*)(Ts + (baserow + 1) * ST))[ic];
                        float4 t2 = ((const float4*)(Ts + (baserow + 2) * ST))[ic];
                        float4 t3 = ((const float4*)(Ts + (baserow + 3) * ST))[ic];
                        a0 += t0.x * wv.x + t0.y * wv.y + t0.z * wv.z + t0.w * wv.w;
                        a1 += t1.x * wv.x + t1.y * wv.y + t1.z * wv.z + t1.w * wv.w;
                        a2 += t2.x * wv.x + t2.y * wv.y + t2.z * wv.z + t2.w * wv.w;
                        a3 += t3.x * wv.x + t3.y * wv.y + t3.z * wv.z + t3.w * wv.w;
                    }
                    float av[4] = {a0, a1, a2, a3};
#pragma unroll
                    for (int q = 0; q < 4; q++) {
                        int r = baserow + q;
                        int node = ((r >> 4) * G + blockIdx.x) * NPB + (r & 15);
                        if (r < nrows && node < n) {
                            if (k == 0) {
                                acc[node * OUTS + j] = av[q] + __ldg(&bias[j]);
                            } else if (k == K - 1) {
                                hout[node * OUTS + j] =
                                    silu_f(acc[node * OUTS + j] + av[q]);
                            } else {
                                acc[node * OUTS + j] += av[q];
                            }
                        }
                    }
                }
            }
        }

        bar_wait(gen);   // all blocks' T_k visible; this block's GEMM done

        // stage W_{k+1} transposed + zero-padded
        if (k + 1 < K) {
            for (int idx = tid; idx < INP * OUT; idx += TPB) {
                int i = idx / OUT, j2 = idx % OUT;
                WsT[j2 * ST + i] =
                    (i < INW) ? W[(k + 1) * INW * OUT + i * OUT + j2] : 0.f;
            }
        }

        if (k >= 1) { prv = src; src = dst; }
    }

    // publish hout (written after the last arrive) before caller reads
    gbar_full(G);
}

// ---------------- the single fused kernel -------------------------------------
__global__ __launch_bounds__(TPB, BPS)
void fused_all(const float* __restrict__ x, const void* __restrict__ ei,
               const float* __restrict__ ew,
               const float* __restrict__ W1, const float* __restrict__ b1,
               const float* __restrict__ W2, const float* __restrict__ b2,
               const float* __restrict__ W3, const float* __restrict__ b3,
               const float* __restrict__ W4,
               float* __restrict__ out, int n, int E, int G) {
    __shared__ __align__(16) float Ts[TSR * ST];
    __shared__ __align__(16) float WsT[64 * ST];
    __shared__ int ssum[TPB];

    int tid = threadIdx.x;
    int bid = blockIdx.x;
    int gsz = G * TPB;
    int gid = bid * TPB + tid;

    // phase 0: zero counters + detect int64-vs-int32 edge_index layout
    for (int i = gid; i < n; i += gsz) { g_deg[i] = 0.f; g_cnt[i] = 0; }
    if (bid == 0) {
        __shared__ int bad;
        if (tid == 0) bad = 0;
        __syncthreads();
        int nsamp = E / 2;
        if (nsamp > 4096) nsamp = 4096;
        const int* p32 = (const int*)ei;
        for (int i = tid; i < nsamp; i += TPB)
            if (p32[2 * i + 1] != 0) bad = 1;
        __syncthreads();
        if (tid == 0) g_is64 = (bad == 0) ? 1 : 0;
    }
    gbar_full(G);

    // phase 1: decode edges (clamped) + degree & in-count
    {
        int is64 = g_is64;
        for (int e = gid; e < E; e += gsz) {
            int s, d;
            if (is64) {
                const long long* p = (const long long*)ei;
                s = (int)p[e];
                d = (int)p[(long long)E + e];
            } else {
                const int* p = (const int*)ei;
                s = p[e];
                d = p[E + e];
            }
            s = (s < 0) ? 0 : ((s >= n) ? n - 1 : s);
            d = (d < 0) ? 0 : ((d >= n) ? n - 1 : d);
            g_srcd[e] = s;
            g_dstd[e] = d;
            atomicAdd(&g_deg[s], ew[e]);
            atomicAdd(&g_cnt[d], 1);
        }
    }
    gbar_full(G);

    // phase 2: dis + exclusive scan (block 0 only)
    if (bid == 0) {
        for (int i = tid; i < n; i += TPB) {
            float d = g_deg[i];
            g_dis[i] = (d > 0.f) ? (1.f / sqrtf(d)) : 0.f;
        }
        __syncthreads();
        int chunk = (n + TPB - 1) / TPB;
        int beg = tid * chunk; if (beg > n) beg = n;
        int end = beg + chunk; if (end > n) end = n;
        int s = 0;
        for (int i = beg; i < end; i++) s += g_cnt[i];
        ssum[tid] = s;
        __syncthreads();
        for (int off = 1; off < TPB; off <<= 1) {
            int v = (tid >= off) ? ssum[tid - off] : 0;
            __syncthreads();
            ssum[tid] += v;
            __syncthreads();
        }
        int run = (tid == 0) ? 0 : ssum[tid - 1];
        for (int i = beg; i < end; i++) {
            int c = g_cnt[i];
            g_rowptr[i] = run;
            g_cnt[i] = run;   // cursor for scatter
            run += c;
        }
        if (tid == TPB - 1) g_rowptr[n] = ssum[TPB - 1];
    }
    gbar_full(G);

    // phase 3: scatter packed (col, norm) into CSR order
    for (int e = gid; e < E; e += gsz) {
        int s = g_srcd[e], d = g_dstd[e];
        float nv = -g_dis[s] * ew[e] * g_dis[d];
        int p = atomicAdd(&g_cnt[d], 1);
        g_colw[p] = make_int2(s, __float_as_int(nv));
    }
    gbar_full(G);

    // layer 1: ChebConv(4 -> 64, K=120) + SiLU folded into g_h (stride 64)
    layer_run<4, 4, 64, 64>(x, g_acc, g_h, W1, b1, 120, n, G, Ts, WsT);

    // layer 2: ChebConv(64 -> 60, K=120) + SiLU folded into g_h, OUTPUT STRIDE
    // 64 (cols 60..63 keep stale layer-1 values; bounded under propagate since
    // |lambda(L_hat)| <= 1, and W3 pad rows are staged zero)
    layer_run<64, 64, 60, 64>(g_h, g_acc, g_h, W2, b2, 120, n, G, Ts, WsT);

    // layer 3: ChebConv(60 -> 30, K=20), VECTORIZED via padded stride 64;
    // SiLU folded into g_acc (block-owned rows, stride 30)
    layer_run<64, 60, 30, 30>(g_h, g_acc, g_acc, W3, b3, 20, n, G, Ts, WsT);

    // layer 4: ChebConv(30 -> 1, K=1) + sigmoid
    for (int i = gid; i < n; i += gsz) {
        float s = 0.f;
        const float* hp = g_acc + i * 30;
#pragma unroll
        for (int k = 0; k < 30; k++) s += hp[k] * __ldg(&W4[k]);
        out[i] = 1.f / (1.f + expf(-s));
    }
}

// ---------------- host orchestration ------------------------------------------
extern "C" void kernel_launch(void* const* d_in, const int* in_sizes, int n_in,
                              void* d_out, int out_size) {
    const float* x  = (const float*)d_in[0];
    const void*  ei = d_in[1];
    const float* ew = (const float*)d_in[2];
    const float* W1 = (const float*)d_in[3];
    const float* b1 = (const float*)d_in[4];
    const float* W2 = (const float*)d_in[5];
    const float* b2 = (const float*)d_in[6];
    const float* W3 = (const float*)d_in[7];
    const float* b3 = (const float*)d_in[8];
    const float* W4 = (const float*)d_in[9];
    float* out = (float*)d_out;

    int n = in_sizes[0] / 4;   // 10000
    int E = in_sizes[2];       // 320000

    static int G = 0;
    if (G == 0) {
        int dev = 0;
        cudaGetDevice(&dev);
        int sms = 0;
        cudaDeviceGetAttribute(&sms, cudaDevAttrMultiProcessorCount, dev);
        int bps = 0;
        cudaOccupancyMaxActiveBlocksPerMultiprocessor(&bps, fused_all, TPB, 0);
        if (sms <= 0) sms = 148;
        if (bps <= 0) bps = 1;
        if (bps > BPS) bps = BPS;
        G = sms * bps;
        // need tiles = ceil(n/(G*16)) <= 2  ->  G >= n/32
        int min_g = (10000 + 31) / 32;
        if (G < min_g) G = min_g;
    }

    fused_all<<<G, TPB>>>(x, ei, ew, W1, b1, W2, b2, W3, b3, W4, out, n, E, G);
}